// round 4
// baseline (speedup 1.0000x reference)
#include <cuda_runtime.h>
#include <cuda_bf16.h>
#include <cuda_fp8.h>
#include <cstdint>

#define NUM_EMB 4096
#define DIM     256
#define NROWS   65536
#define Q_ELEMS (NROWS * DIM)
#define THRESH  0.025f

#define BM 128
#define BN 128
#define KITERS  16                 // per chunk: 8 bf16 (k32) + 4 fp8 (k64) + 4 fp8 (k64)
#define NCHUNKS 32
#define TOTAL_ITERS (NCHUNKS * KITERS)

// ---- device scratch ----
// per embedding, 1024B: [eh bf16 512B | el e5m2 256B | eh e4m3 256B]
__device__ uint8_t g_Ball[NUM_EMB * 1024];
__device__ float g_half_sq[NUM_EMB];
__device__ int   g_best[NROWS];
__device__ int   g_flag_rows[NROWS];
__device__ int   g_flag_count;
__device__ float g_loss;

// ---- smem layout (dynamic) ----
// per row 1024B: [xh bf16 512B | xh e4m3 256B | xl e5m2 256B], swizzled granules
#define SM_A     0
#define A_BYTES  (128 * 1024)
#define SM_B     A_BYTES
#define B_STAGE  8192               // 128 n x 64 B slice
#define SM_HS    (SM_B + 3 * B_STAGE)
#define SMEM_TOTAL (SM_HS + 16384)

__device__ __forceinline__ uint32_t smem_to_u32(const void* p) {
    uint32_t a;
    asm("{ .reg .u64 t; cvta.to.shared.u64 t, %1; cvt.u32.u64 %0, t; }" : "=r"(a) : "l"(p));
    return a;
}

#define LDSM_X4(r0, r1, r2, r3, addr) \
    asm volatile("ldmatrix.sync.aligned.m8n8.x4.shared.b16 {%0,%1,%2,%3}, [%4];" \
        : "=r"(r0), "=r"(r1), "=r"(r2), "=r"(r3) : "r"(addr))

#define MMA_BF16(d, a, b0, b1) \
    asm volatile("mma.sync.aligned.m16n8k16.row.col.f32.bf16.bf16.f32 " \
        "{%0,%1,%2,%3},{%4,%5,%6,%7},{%8,%9},{%0,%1,%2,%3};" \
        : "+f"((d)[0]), "+f"((d)[1]), "+f"((d)[2]), "+f"((d)[3]) \
        : "r"((a)[0]), "r"((a)[1]), "r"((a)[2]), "r"((a)[3]), "r"(b0), "r"(b1))

// A = e4m3 (xh), B = e5m2 (el)
#define MMA_F8_45(d, a, b0, b1) \
    asm volatile("mma.sync.aligned.m16n8k32.row.col.f32.e4m3.e5m2.f32 " \
        "{%0,%1,%2,%3},{%4,%5,%6,%7},{%8,%9},{%0,%1,%2,%3};" \
        : "+f"((d)[0]), "+f"((d)[1]), "+f"((d)[2]), "+f"((d)[3]) \
        : "r"((a)[0]), "r"((a)[1]), "r"((a)[2]), "r"((a)[3]), "r"(b0), "r"(b1))

// A = e5m2 (xl), B = e4m3 (eh)
#define MMA_F8_54(d, a, b0, b1) \
    asm volatile("mma.sync.aligned.m16n8k32.row.col.f32.e5m2.e4m3.f32 " \
        "{%0,%1,%2,%3},{%4,%5,%6,%7},{%8,%9},{%0,%1,%2,%3};" \
        : "+f"((d)[0]), "+f"((d)[1]), "+f"((d)[2]), "+f"((d)[3]) \
        : "r"((a)[0]), "r"((a)[1]), "r"((a)[2]), "r"((a)[3]), "r"(b0), "r"(b1))

#define CP_ASYNC16(dst, src) \
    asm volatile("cp.async.cg.shared.global [%0], [%1], 16;" :: "r"(dst), "l"(src) : "memory")
#define CP_ASYNC_COMMIT() asm volatile("cp.async.commit_group;" ::: "memory")
#define CP_ASYNC_WAIT1()  asm volatile("cp.async.wait_group 1;" ::: "memory")

__device__ __forceinline__ uint8_t f2e4m3(float f) {
    __nv_fp8_e4m3 v(f); return *(uint8_t*)&v;
}
__device__ __forceinline__ uint8_t f2e5m2(float f) {
    __nv_fp8_e5m2 v(f); return *(uint8_t*)&v;
}

// ---------------------------------------------------------------------------
// prep: 0.5*|e|^2 + zero accumulators
// ---------------------------------------------------------------------------
__global__ void vq_prep_kernel(const float* __restrict__ E) {
    if (blockIdx.x == 0 && threadIdx.x == 0) { g_loss = 0.0f; g_flag_count = 0; }
    int warp = (blockIdx.x * blockDim.x + threadIdx.x) >> 5;
    int lane = threadIdx.x & 31;
    if (warp >= NUM_EMB) return;
    const float4* row = (const float4*)(E + (size_t)warp * DIM);
    float s = 0.0f;
#pragma unroll
    for (int i = 0; i < 2; i++) {
        float4 v = row[lane + 32 * i];
        s += v.x * v.x + v.y * v.y + v.z * v.z + v.w * v.w;
    }
#pragma unroll
    for (int o = 16; o > 0; o >>= 1) s += __shfl_xor_sync(0xffffffffu, s, o);
    if (lane == 0) g_half_sq[warp] = 0.5f * s;
}

// ---------------------------------------------------------------------------
// splitE: E fp32 -> g_Ball  [eh bf16 | el e5m2 | eh e4m3]
// thread handles 8 consecutive k of one embedding
// ---------------------------------------------------------------------------
__global__ void vq_splitE_kernel(const float* __restrict__ E) {
    int i = blockIdx.x * blockDim.x + threadIdx.x;   // 4096 * 32
    if (i >= NUM_EMB * 32) return;
    int j = i >> 5, q8 = i & 31;
    const float4* src = (const float4*)(E + (size_t)j * DIM + q8 * 8);
    float f[8];
    { float4 v = src[0]; f[0]=v.x; f[1]=v.y; f[2]=v.z; f[3]=v.w; }
    { float4 v = src[1]; f[4]=v.x; f[5]=v.y; f[6]=v.z; f[7]=v.w; }
    __nv_bfloat16 h[8];
    uint8_t el8[8], eh8[8];
#pragma unroll
    for (int k = 0; k < 8; k++) {
        h[k] = __float2bfloat16(f[k]);
        float hf = __bfloat162float(h[k]);
        el8[k] = f2e5m2(f[k] - hf);
        eh8[k] = f2e4m3(hf);
    }
    uint8_t* base = g_Ball + (size_t)j * 1024;
    *(uint4*)(base + q8 * 16)        = *(uint4*)h;
    *(uint2*)(base + 512 + q8 * 8)   = *(uint2*)el8;
    *(uint2*)(base + 768 + q8 * 8)   = *(uint2*)eh8;
}

// ---------------------------------------------------------------------------
// B stage loader: slice kt (64B per embedding row), 128 rows -> 8KB stage
// ---------------------------------------------------------------------------
__device__ __forceinline__ void load_B_stage(uint32_t sb, int stage, int chunk,
                                             int kt, int tid) {
    const uint8_t* src0 = g_Ball + (size_t)(chunk * BN) * 1024 + kt * 64;
    uint32_t dstb = sb + SM_B + stage * B_STAGE;
#pragma unroll
    for (int j = 0; j < 2; j++) {
        int cid = tid + 256 * j;
        int n = cid >> 2, c = cid & 3;
        const void* src = src0 + (size_t)n * 1024 + c * 16;
        uint32_t dst = dstb + (uint32_t)((n >> 1) * 128)
                     + ((uint32_t)(((((n & 1) << 2) | c) ^ ((n >> 1) & 7))) << 4);
        CP_ASYNC16(dst, src);
    }
}

// ---------------------------------------------------------------------------
// main: fused bf16+fp8 mma.sync GEMM + top-2 argmax
// ---------------------------------------------------------------------------
__global__ __launch_bounds__(256, 1)
void vq_main_kernel(const float* __restrict__ X, float* __restrict__ out_idx_f) {
    extern __shared__ char smem[];
    uint32_t sb = smem_to_u32(smem);
    const int tid = threadIdx.x;
    const int l = tid & 31, wid = tid >> 5;
    const int wM = wid & 1, wN = wid >> 1;
    const int row0 = blockIdx.x * BM;

    // half_sq -> smem
    for (int i = tid; i < NUM_EMB / 4; i += 256)
        ((float4*)(smem + SM_HS))[i] = ((const float4*)g_half_sq)[i];

    // A fill pass 1: xh bf16 at granules 0..63 (chunks 0..31)
    for (int i = tid; i < BM * 64; i += 256) {
        int row = i >> 6, q = i & 63;
        float4 v = ((const float4*)(X + (size_t)(row0 + row) * DIM))[q];
        __nv_bfloat16 h[4];
        float f[4] = {v.x, v.y, v.z, v.w};
#pragma unroll
        for (int k = 0; k < 4; k++) h[k] = __float2bfloat16(f[k]);
        int rsw = row & 7;
        int g = q, c = g >> 1;
        uint32_t off = (uint32_t)row * 1024 + ((uint32_t)(c >> 3) << 7)
                     + ((uint32_t)((c & 7) ^ rsw) << 4) + ((uint32_t)(g & 1) << 3);
        *(uint2*)(smem + SM_A + off) = *(uint2*)h;
    }
    // A fill pass 2: xh e4m3 at granules 64..95, xl e5m2 at granules 96..127
    for (int i = tid; i < BM * 32; i += 256) {
        int row = i >> 5, q8 = i & 31;
        const float4* src = (const float4*)(X + (size_t)(row0 + row) * DIM + q8 * 8);
        float f[8];
        { float4 v = src[0]; f[0]=v.x; f[1]=v.y; f[2]=v.z; f[3]=v.w; }
        { float4 v = src[1]; f[4]=v.x; f[5]=v.y; f[6]=v.z; f[7]=v.w; }
        uint8_t xh8[8], xl8[8];
#pragma unroll
        for (int k = 0; k < 8; k++) {
            float hf = __bfloat162float(__float2bfloat16(f[k]));
            xh8[k] = f2e4m3(hf);
            xl8[k] = f2e5m2(f[k] - hf);
        }
        int rsw = row & 7;
        {
            int g = 64 + q8, c = g >> 1;
            uint32_t off = (uint32_t)row * 1024 + ((uint32_t)(c >> 3) << 7)
                         + ((uint32_t)((c & 7) ^ rsw) << 4) + ((uint32_t)(g & 1) << 3);
            *(uint2*)(smem + SM_A + off) = *(uint2*)xh8;
        }
        {
            int g = 96 + q8, c = g >> 1;
            uint32_t off = (uint32_t)row * 1024 + ((uint32_t)(c >> 3) << 7)
                         + ((uint32_t)((c & 7) ^ rsw) << 4) + ((uint32_t)(g & 1) << 3);
            *(uint2*)(smem + SM_A + off) = *(uint2*)xl8;
        }
    }

    // prefetch B stages for it = 0, 1
    load_B_stage(sb, 0, 0, 0, tid); CP_ASYNC_COMMIT();
    load_B_stage(sb, 1, 0, 1, tid); CP_ASYNC_COMMIT();

    const int clA = l >> 4;
    const int lsw = l & 7;
    uint32_t abase[4];
#pragma unroll
    for (int mt = 0; mt < 4; mt++) {
        int rowA = wM * 64 + mt * 16 + (l & 15);
        abase[mt] = sb + SM_A + (uint32_t)rowA * 1024;
    }
    uint32_t bblk[2], bswz[2], bc4[2];
#pragma unroll
    for (int ntp = 0; ntp < 2; ntp++) {
        int nloc = wN * 32 + ntp * 16 + (l & 15);
        bblk[ntp] = (uint32_t)(nloc >> 1) * 128;
        bswz[ntp] = (uint32_t)((nloc >> 1) & 7);
        bc4[ntp]  = (uint32_t)((nloc & 1) << 2);
    }

    float acc[4][4][4];
#pragma unroll
    for (int a = 0; a < 4; a++)
#pragma unroll
        for (int b = 0; b < 4; b++)
#pragma unroll
            for (int c = 0; c < 4; c++) acc[a][b][c] = 0.0f;

    float b1[8], b2[8];
    int   idx1[8];
#pragma unroll
    for (int s = 0; s < 8; s++) { b1[s] = -3.402823e38f; b2[s] = -3.402823e38f; idx1[s] = 0; }

    int chunk = 0, kt = 0;
    int pf_chunk = 0, pf_kt = 2;
    int buf = 0, pbuf = 2;
    const float* hsp = (const float*)(smem + SM_HS);

    for (int it = 0; it < TOTAL_ITERS; it++) {
        CP_ASYNC_WAIT1();
        __syncthreads();

        uint32_t bbuf = sb + SM_B + buf * B_STAGE;
        // A granule-chunk base for this iter (16B-chunk units within the row)
        int cA0 = (kt < 8) ? kt * 4 : ((kt < 12) ? 32 + (kt - 8) * 4 : 48 + (kt - 12) * 4);
#pragma unroll
        for (int s = 0; s < 2; s++) {
            int cA = cA0 + s * 2 + clA;
            uint32_t offA = ((uint32_t)(cA >> 3) << 7) | ((uint32_t)((cA & 7) ^ lsw) << 4);
            uint32_t a_[4][4];
#pragma unroll
            for (int mt = 0; mt < 4; mt++)
                LDSM_X4(a_[mt][0], a_[mt][1], a_[mt][2], a_[mt][3], abase[mt] + offA);
            uint32_t cB = (uint32_t)(s * 2 + clA);
            uint32_t bf[4][2];
#pragma unroll
            for (int ntp = 0; ntp < 2; ntp++) {
                uint32_t addr = bbuf + bblk[ntp] + (((bc4[ntp] | cB) ^ bswz[ntp]) << 4);
                uint32_t r0, r1, r2, r3;
                LDSM_X4(r0, r1, r2, r3, addr);
                bf[2 * ntp][0] = r0; bf[2 * ntp][1] = r2;
                bf[2 * ntp + 1][0] = r1; bf[2 * ntp + 1][1] = r3;
            }
            if (kt < 8) {
#pragma unroll
                for (int mt = 0; mt < 4; mt++)
#pragma unroll
                    for (int nt = 0; nt < 4; nt++)
                        MMA_BF16(acc[mt][nt], a_[mt], bf[nt][0], bf[nt][1]);
            } else if (kt < 12) {
#pragma unroll
                for (int mt = 0; mt < 4; mt++)
#pragma unroll
                    for (int nt = 0; nt < 4; nt++)
                        MMA_F8_45(acc[mt][nt], a_[mt], bf[nt][0], bf[nt][1]);
            } else {
#pragma unroll
                for (int mt = 0; mt < 4; mt++)
#pragma unroll
                    for (int nt = 0; nt < 4; nt++)
                        MMA_F8_54(acc[mt][nt], a_[mt], bf[nt][0], bf[nt][1]);
            }
        }

        if (it + 2 < TOTAL_ITERS) {
            load_B_stage(sb, pbuf, pf_chunk, pf_kt, tid);
            if (++pf_kt == KITERS) { pf_kt = 0; pf_chunk++; }
        }
        CP_ASYNC_COMMIT();
        pbuf = (pbuf == 2) ? 0 : pbuf + 1;
        buf  = (buf == 2) ? 0 : buf + 1;

        if (kt == KITERS - 1) {
            int nbase = chunk * BN + wN * 32 + (l & 3) * 2;
#pragma unroll
            for (int mt = 0; mt < 4; mt++)
#pragma unroll
                for (int rh = 0; rh < 2; rh++) {
                    int slot = mt * 2 + rh;
                    float lb1 = b1[slot], lb2 = b2[slot];
                    int li = idx1[slot];
#pragma unroll
                    for (int nt = 0; nt < 4; nt++)
#pragma unroll
                        for (int cj = 0; cj < 2; cj++) {
                            int n = nbase + nt * 8 + cj;
                            float sc = acc[mt][nt][rh * 2 + cj] - hsp[n];
                            if (sc > lb1) { lb2 = lb1; lb1 = sc; li = n; }
                            else if (sc > lb2) lb2 = sc;
                        }
                    b1[slot] = lb1; b2[slot] = lb2; idx1[slot] = li;
                }
#pragma unroll
            for (int a = 0; a < 4; a++)
#pragma unroll
                for (int b = 0; b < 4; b++)
#pragma unroll
                    for (int c = 0; c < 4; c++) acc[a][b][c] = 0.0f;
            chunk++; kt = 0;
        } else kt++;
    }

    __syncthreads();

#pragma unroll
    for (int d = 1; d <= 2; d <<= 1) {
#pragma unroll
        for (int s = 0; s < 8; s++) {
            float ov1 = __shfl_xor_sync(0xffffffffu, b1[s], d);
            float ov2 = __shfl_xor_sync(0xffffffffu, b2[s], d);
            int   oi  = __shfl_xor_sync(0xffffffffu, idx1[s], d);
            if (ov1 > b1[s]) { b2[s] = fmaxf(b1[s], ov2); b1[s] = ov1; idx1[s] = oi; }
            else             { b2[s] = fmaxf(b2[s], ov1); }
        }
    }
    float* rv1 = (float*)(smem + SM_B);
    float* rv2 = (float*)(smem + SM_B + 2048);
    int*   ri  = (int*)  (smem + SM_B + 4096);
    if ((l & 3) == 0) {
#pragma unroll
        for (int mt = 0; mt < 4; mt++)
#pragma unroll
            for (int rh = 0; rh < 2; rh++) {
                int slot = mt * 2 + rh;
                int row = wM * 64 + mt * 16 + (l >> 2) + rh * 8;
                rv1[row * 4 + wN] = b1[slot];
                rv2[row * 4 + wN] = b2[slot];
                ri [row * 4 + wN] = idx1[slot];
            }
    }
    __syncthreads();
    if (tid < BM) {
        float v1 = -3.402823e38f, v2 = -3.402823e38f;
        int bi = 0;
#pragma unroll
        for (int w = 0; w < 4; w++) {
            float w1 = rv1[tid * 4 + w], w2 = rv2[tid * 4 + w];
            int wi = ri[tid * 4 + w];
            if (w1 > v1) { v2 = fmaxf(v1, w2); v1 = w1; bi = wi; }
            else         { v2 = fmaxf(v2, w1); }
        }
        int grow = row0 + tid;
        g_best[grow] = bi;
        out_idx_f[grow] = (float)bi;
        if (v1 - v2 < THRESH) {
            int p = atomicAdd(&g_flag_count, 1);
            g_flag_rows[p] = grow;
        }
    }
}

// ---------------------------------------------------------------------------
// exact fp32 recompute for near-tie rows (no spills: unroll 8, warp reduce)
// ---------------------------------------------------------------------------
__global__ void vq_fallback_kernel(const float* __restrict__ X,
                                   const float* __restrict__ E,
                                   float* __restrict__ out_idx_f) {
    __shared__ float xr[DIM];
    __shared__ float wv[8];
    __shared__ int   wi_[8];
    int cnt = g_flag_count;
    for (int f = blockIdx.x; f < cnt; f += gridDim.x) {
        int row = g_flag_rows[f];
        __syncthreads();
        if (threadIdx.x < DIM) xr[threadIdx.x] = X[(size_t)row * DIM + threadIdx.x];
        __syncthreads();
        float bv = -3.402823e38f;
        int bi = 0;
        for (int j = threadIdx.x; j < NUM_EMB; j += 256) {
            const float4* e4 = (const float4*)(E + (size_t)j * DIM);
            float dot = 0.0f;
#pragma unroll 8
            for (int k = 0; k < 64; k++) {
                float4 e = e4[k];
                dot += xr[k * 4 + 0] * e.x + xr[k * 4 + 1] * e.y
                     + xr[k * 4 + 2] * e.z + xr[k * 4 + 3] * e.w;
            }
            float sc = dot - g_half_sq[j];
            if (sc > bv) { bv = sc; bi = j; }
        }
#pragma unroll
        for (int o = 16; o > 0; o >>= 1) {
            float ov = __shfl_xor_sync(0xffffffffu, bv, o);
            int   oi = __shfl_xor_sync(0xffffffffu, bi, o);
            if (ov > bv || (ov == bv && oi < bi)) { bv = ov; bi = oi; }
        }
        if ((threadIdx.x & 31) == 0) { wv[threadIdx.x >> 5] = bv; wi_[threadIdx.x >> 5] = bi; }
        __syncthreads();
        if (threadIdx.x == 0) {
            float fbv = wv[0]; int fbi = wi_[0];
#pragma unroll
            for (int t = 1; t < 8; t++)
                if (wv[t] > fbv || (wv[t] == fbv && wi_[t] < fbi)) { fbv = wv[t]; fbi = wi_[t]; }
            g_best[row] = fbi;
            out_idx_f[row] = (float)fbi;
        }
        __syncthreads();
    }
}

// ---------------------------------------------------------------------------
// gather + codebook loss
// ---------------------------------------------------------------------------
__global__ void vq_gather_kernel(const float* __restrict__ X,
                                 const float* __restrict__ E,
                                 float* __restrict__ outQ) {
    __shared__ float bsum[8];
    int warp = threadIdx.x >> 5;
    int lane = threadIdx.x & 31;
    int row = blockIdx.x * 8 + warp;
    int idx = g_best[row];
    const float4* e4 = (const float4*)(E + (size_t)idx * DIM);
    const float4* x4 = (const float4*)(X + (size_t)row * DIM);
    float4*       o4 = (float4*)(outQ + (size_t)row * DIM);
    float s = 0.0f;
#pragma unroll
    for (int i = 0; i < 2; i++) {
        float4 e = e4[lane + 32 * i];
        float4 x = x4[lane + 32 * i];
        o4[lane + 32 * i] = e;
        float dx = e.x - x.x, dy = e.y - x.y, dz = e.z - x.z, dw = e.w - x.w;
        s += dx * dx + dy * dy + dz * dz + dw * dw;
    }
#pragma unroll
    for (int o = 16; o > 0; o >>= 1) s += __shfl_xor_sync(0xffffffffu, s, o);
    if (lane == 0) bsum[warp] = s;
    __syncthreads();
    if (threadIdx.x == 0) {
        float t = 0.0f;
#pragma unroll
        for (int i = 0; i < 8; i++) t += bsum[i];
        atomicAdd(&g_loss, t);
    }
}

__global__ void vq_finalize_kernel(float* __restrict__ out_loss) {
    *out_loss = g_loss * (1.0f / (float)Q_ELEMS);
}

extern "C" void kernel_launch(void* const* d_in, const int* in_sizes, int n_in,
                              void* d_out, int out_size) {
    const float* X = (const float*)d_in[0];
    const float* E = (const float*)d_in[1];
    float* out     = (float*)d_out;
    float* outQ    = out;
    float* outLoss = out + Q_ELEMS;
    float* outIdxF = out + Q_ELEMS + 1;

    cudaFuncSetAttribute(vq_main_kernel,
                         cudaFuncAttributeMaxDynamicSharedMemorySize, SMEM_TOTAL);

    vq_prep_kernel<<<NUM_EMB / 8, 256>>>(E);
    vq_splitE_kernel<<<NUM_EMB * 32 / 256, 256>>>(E);
    vq_main_kernel<<<NROWS / BM, 256, SMEM_TOTAL>>>(X, outIdxF);
    vq_fallback_kernel<<<1024, 256>>>(X, E, outIdxF);
    vq_gather_kernel<<<NROWS / 8, 256>>>(X, E, outQ);
    vq_finalize_kernel<<<1, 1>>>(outLoss);
}

// round 5
// speedup vs baseline: 2.5608x; 2.5608x over previous
#include <cuda_runtime.h>
#include <cuda_bf16.h>
#include <cstdint>

#define NUM_EMB 4096
#define DIM     256
#define NROWS   65536
#define Q_ELEMS (NROWS * DIM)
#define DELTA   0.75f
#define CAP     48

#define BM 128
#define BN 128
#define KITERS  8                  // 256 K / 32 per iter
#define NCHUNKS 32
#define TOTAL_ITERS (NCHUNKS * KITERS)

// ---- device scratch ----
__device__ __nv_bfloat16 g_Ebf[NUM_EMB * DIM];     // eh bf16
__device__ float  g_half_sq[NUM_EMB];
__device__ float  g_rowmax[NROWS];
__device__ int    g_cnt[NROWS];
__device__ uint2  g_cand[(size_t)NROWS * CAP];     // {score bits, n}
__device__ int    g_ovf[NROWS];
__device__ int    g_ovf_cnt;
__device__ float  g_loss;

// ---- smem layout (dynamic) ----
#define SM_A     0
#define A_BYTES  (128 * 512)        // 128 rows x 256 bf16, swizzled
#define SM_B     A_BYTES
#define B_STAGE  8192               // 128 n x 32 k bf16
#define SM_HS    (SM_B + 3 * B_STAGE)
#define SM_RM    (SM_HS + 16384)    // 128 x uint rowmax
#define SMEM_TOTAL (SM_RM + 512)

__device__ __forceinline__ uint32_t smem_to_u32(const void* p) {
    uint32_t a;
    asm("{ .reg .u64 t; cvta.to.shared.u64 t, %1; cvt.u32.u64 %0, t; }" : "=r"(a) : "l"(p));
    return a;
}

#define LDSM_X4(r0, r1, r2, r3, addr) \
    asm volatile("ldmatrix.sync.aligned.m8n8.x4.shared.b16 {%0,%1,%2,%3}, [%4];" \
        : "=r"(r0), "=r"(r1), "=r"(r2), "=r"(r3) : "r"(addr))

#define MMA_BF16(d, a, b0, b1) \
    asm volatile("mma.sync.aligned.m16n8k16.row.col.f32.bf16.bf16.f32 " \
        "{%0,%1,%2,%3},{%4,%5,%6,%7},{%8,%9},{%0,%1,%2,%3};" \
        : "+f"((d)[0]), "+f"((d)[1]), "+f"((d)[2]), "+f"((d)[3]) \
        : "r"((a)[0]), "r"((a)[1]), "r"((a)[2]), "r"((a)[3]), "r"(b0), "r"(b1))

#define CP_ASYNC16(dst, src) \
    asm volatile("cp.async.cg.shared.global [%0], [%1], 16;" :: "r"(dst), "l"(src) : "memory")
#define CP_ASYNC_COMMIT() asm volatile("cp.async.commit_group;" ::: "memory")
#define CP_ASYNC_WAIT1()  asm volatile("cp.async.wait_group 1;" ::: "memory")

// monotone float<->uint encoding for atomicMax
__device__ __forceinline__ uint32_t fenc(float f) {
    uint32_t u = __float_as_uint(f);
    return (u & 0x80000000u) ? ~u : (u | 0x80000000u);
}
__device__ __forceinline__ float fdec(uint32_t k) {
    uint32_t u = (k & 0x80000000u) ? (k & 0x7fffffffu) : ~k;
    return __uint_as_float(u);
}

// ---------------------------------------------------------------------------
// prep: 0.5*|e|^2, zero counters
// ---------------------------------------------------------------------------
__global__ void vq_prep_kernel(const float* __restrict__ E) {
    int gid = blockIdx.x * blockDim.x + threadIdx.x;
    if (gid == 0) { g_loss = 0.0f; g_ovf_cnt = 0; }
    if (gid < NROWS) g_cnt[gid] = 0;
    int warp = gid >> 5;
    int lane = threadIdx.x & 31;
    if (warp >= NUM_EMB) return;
    const float4* row = (const float4*)(E + (size_t)warp * DIM);
    float s = 0.0f;
#pragma unroll
    for (int i = 0; i < 2; i++) {
        float4 v = row[lane + 32 * i];
        s += v.x * v.x + v.y * v.y + v.z * v.z + v.w * v.w;
    }
#pragma unroll
    for (int o = 16; o > 0; o >>= 1) s += __shfl_xor_sync(0xffffffffu, s, o);
    if (lane == 0) g_half_sq[warp] = 0.5f * s;
}

// ---------------------------------------------------------------------------
// splitE: E fp32 -> bf16
// ---------------------------------------------------------------------------
__global__ void vq_splitE_kernel(const float* __restrict__ E) {
    int i = blockIdx.x * blockDim.x + threadIdx.x;   // 4096*64 float4s
    if (i >= NUM_EMB * 64) return;
    float4 v = ((const float4*)E)[i];
    __nv_bfloat16 h[4] = {__float2bfloat16(v.x), __float2bfloat16(v.y),
                          __float2bfloat16(v.z), __float2bfloat16(v.w)};
    ((uint2*)g_Ebf)[i] = *(uint2*)h;
}

// ---------------------------------------------------------------------------
// B stage loader
// ---------------------------------------------------------------------------
__device__ __forceinline__ void load_B_stage(uint32_t sb, int stage, int chunk,
                                             int kt, int tid) {
    const __nv_bfloat16* src0 = g_Ebf + (size_t)(chunk * BN) * DIM + kt * 32;
    uint32_t dstb = sb + SM_B + stage * B_STAGE;
#pragma unroll
    for (int j = 0; j < 2; j++) {
        int cid = tid + 256 * j;
        int n = cid >> 2, c = cid & 3;
        const void* src = src0 + (size_t)n * DIM + c * 8;
        uint32_t dst = dstb + (uint32_t)((n >> 1) * 128)
                     + ((uint32_t)(((((n & 1) << 2) | c) ^ ((n >> 1) & 7))) << 4);
        CP_ASYNC16(dst, src);
    }
}

// ---------------------------------------------------------------------------
// main: bf16 screening GEMM + candidate collection
// ---------------------------------------------------------------------------
__global__ __launch_bounds__(256, 1)
void vq_main_kernel(const float* __restrict__ X) {
    extern __shared__ char smem[];
    uint32_t sb = smem_to_u32(smem);
    const int tid = threadIdx.x;
    const int l = tid & 31, wid = tid >> 5;
    const int wM = wid & 1, wN = wid >> 1;
    const int row0 = blockIdx.x * BM;
    uint32_t* rmax = (uint32_t*)(smem + SM_RM);

    for (int i = tid; i < NUM_EMB / 4; i += 256)
        ((float4*)(smem + SM_HS))[i] = ((const float4*)g_half_sq)[i];
    if (tid < BM) rmax[tid] = 0u;    // below fenc of any real float

    // A fill: xh bf16, swizzled, row stride 512B
    for (int i = tid; i < BM * 64; i += 256) {
        int row = i >> 6, q = i & 63;
        float4 v = ((const float4*)(X + (size_t)(row0 + row) * DIM))[q];
        __nv_bfloat16 h[4] = {__float2bfloat16(v.x), __float2bfloat16(v.y),
                              __float2bfloat16(v.z), __float2bfloat16(v.w)};
        int c = q >> 1;
        uint32_t off = (uint32_t)row * 512 + ((uint32_t)(c >> 3) << 7)
                     + ((uint32_t)((c & 7) ^ (row & 7)) << 4) + ((uint32_t)(q & 1) << 3);
        *(uint2*)(smem + SM_A + off) = *(uint2*)h;
    }

    load_B_stage(sb, 0, 0, 0, tid); CP_ASYNC_COMMIT();
    load_B_stage(sb, 1, 0, 1, tid); CP_ASYNC_COMMIT();

    const int clA = l >> 4;
    const int lsw = l & 7;
    uint32_t abase[4];
#pragma unroll
    for (int mt = 0; mt < 4; mt++) {
        int rowA = wM * 64 + mt * 16 + (l & 15);
        abase[mt] = sb + SM_A + (uint32_t)rowA * 512;
    }
    uint32_t bblk[2], bswz[2], bc4[2];
#pragma unroll
    for (int ntp = 0; ntp < 2; ntp++) {
        int nloc = wN * 32 + ntp * 16 + (l & 15);
        bblk[ntp] = (uint32_t)(nloc >> 1) * 128;
        bswz[ntp] = (uint32_t)((nloc >> 1) & 7);
        bc4[ntp]  = (uint32_t)((nloc & 1) << 2);
    }

    float acc[4][4][4];
#pragma unroll
    for (int a = 0; a < 4; a++)
#pragma unroll
        for (int b = 0; b < 4; b++)
#pragma unroll
            for (int c = 0; c < 4; c++) acc[a][b][c] = 0.0f;

    int chunk = 0, kt = 0;
    int pf_chunk = 0, pf_kt = 2;
    int buf = 0, pbuf = 2;
    const float* hsp = (const float*)(smem + SM_HS);

    for (int it = 0; it < TOTAL_ITERS; it++) {
        CP_ASYNC_WAIT1();
        __syncthreads();

        uint32_t bbuf = sb + SM_B + buf * B_STAGE;
        int cA0 = kt * 4;
#pragma unroll
        for (int s = 0; s < 2; s++) {
            int cA = cA0 + s * 2 + clA;
            uint32_t offA = ((uint32_t)(cA >> 3) << 7) | ((uint32_t)((cA & 7) ^ lsw) << 4);
            uint32_t a_[4][4];
#pragma unroll
            for (int mt = 0; mt < 4; mt++)
                LDSM_X4(a_[mt][0], a_[mt][1], a_[mt][2], a_[mt][3], abase[mt] + offA);
            uint32_t cB = (uint32_t)(s * 2 + clA);
            uint32_t bf[4][2];
#pragma unroll
            for (int ntp = 0; ntp < 2; ntp++) {
                uint32_t addr = bbuf + bblk[ntp] + (((bc4[ntp] | cB) ^ bswz[ntp]) << 4);
                uint32_t r0, r1, r2, r3;
                LDSM_X4(r0, r1, r2, r3, addr);
                bf[2 * ntp][0] = r0; bf[2 * ntp][1] = r2;
                bf[2 * ntp + 1][0] = r1; bf[2 * ntp + 1][1] = r3;
            }
#pragma unroll
            for (int mt = 0; mt < 4; mt++)
#pragma unroll
                for (int nt = 0; nt < 4; nt++)
                    MMA_BF16(acc[mt][nt], a_[mt], bf[nt][0], bf[nt][1]);
        }

        if (it + 2 < TOTAL_ITERS) {
            load_B_stage(sb, pbuf, pf_chunk, pf_kt, tid);
            if (++pf_kt == KITERS) { pf_kt = 0; pf_chunk++; }
        }
        CP_ASYNC_COMMIT();
        pbuf = (pbuf == 2) ? 0 : pbuf + 1;
        buf  = (buf == 2) ? 0 : buf + 1;

        if (kt == KITERS - 1) {
            // ---- pass A: scores + per-row max into smem ----
            int nbase = chunk * BN + wN * 32 + (l & 3) * 2;
#pragma unroll
            for (int mt = 0; mt < 4; mt++)
#pragma unroll
                for (int rh = 0; rh < 2; rh++) {
                    int r_loc = wM * 64 + mt * 16 + (l >> 2) + rh * 8;
                    float smax = -3.402823e38f;
#pragma unroll
                    for (int nt = 0; nt < 4; nt++)
#pragma unroll
                        for (int cj = 0; cj < 2; cj++) {
                            float sc = acc[mt][nt][rh * 2 + cj] - hsp[nbase + nt * 8 + cj];
                            acc[mt][nt][rh * 2 + cj] = sc;
                            smax = fmaxf(smax, sc);
                        }
                    atomicMax(&rmax[r_loc], fenc(smax));
                }
            __syncthreads();
            // ---- pass B: append candidates within DELTA of row max ----
#pragma unroll
            for (int mt = 0; mt < 4; mt++)
#pragma unroll
                for (int rh = 0; rh < 2; rh++) {
                    int r_loc = wM * 64 + mt * 16 + (l >> 2) + rh * 8;
                    float window = fdec(rmax[r_loc]) - DELTA;
                    int grow = row0 + r_loc;
#pragma unroll
                    for (int nt = 0; nt < 4; nt++)
#pragma unroll
                        for (int cj = 0; cj < 2; cj++) {
                            float sc = acc[mt][nt][rh * 2 + cj];
                            if (sc > window) {
                                int pos = atomicAdd(&g_cnt[grow], 1);
                                if (pos < CAP) {
                                    g_cand[(size_t)grow * CAP + pos] =
                                        make_uint2(__float_as_uint(sc),
                                                   (uint32_t)(nbase + nt * 8 + cj));
                                }
                            }
                        }
                }
#pragma unroll
            for (int a = 0; a < 4; a++)
#pragma unroll
                for (int b = 0; b < 4; b++)
#pragma unroll
                    for (int c = 0; c < 4; c++) acc[a][b][c] = 0.0f;
            chunk++; kt = 0;
        } else kt++;
    }

    __syncthreads();
    if (tid < BM) g_rowmax[row0 + tid] = fdec(rmax[tid]);
}

// ---------------------------------------------------------------------------
// phase 2: exact fp32 on candidates + gather + loss (1 warp per row)
// ---------------------------------------------------------------------------
__global__ __launch_bounds__(256)
void vq_phase2_kernel(const float* __restrict__ X, const float* __restrict__ E,
                      float* __restrict__ outQ, float* __restrict__ out_idx_f) {
    __shared__ float lsum[8];
    int warp = threadIdx.x >> 5, lane = threadIdx.x & 31;
    int row = blockIdx.x * 8 + warp;
    float lossacc = 0.0f;
    int cnt = g_cnt[row];
    float xr[8];
    const float* xrow = X + (size_t)row * DIM;
#pragma unroll
    for (int j = 0; j < 8; j++) xr[j] = xrow[lane + 32 * j];

    if (cnt > CAP) {
        if (lane == 0) { int p = atomicAdd(&g_ovf_cnt, 1); g_ovf[p] = row; }
    } else {
        float window = g_rowmax[row] - DELTA;
        float best = -3.402823e38f;
        int bidx = NUM_EMB;
        for (int c = 0; c < cnt; c++) {
            uint2 cd = g_cand[(size_t)row * CAP + c];
            float apx = __uint_as_float(cd.x);
            if (apx < window) continue;
            int n = (int)cd.y;
            const float* e = E + (size_t)n * DIM;
            float dot = 0.0f;
#pragma unroll
            for (int j = 0; j < 8; j++) dot = fmaf(xr[j], e[lane + 32 * j], dot);
#pragma unroll
            for (int o = 16; o > 0; o >>= 1) dot += __shfl_xor_sync(0xffffffffu, dot, o);
            float sc = dot - g_half_sq[n];
            if (sc > best || (sc == best && n < bidx)) { best = sc; bidx = n; }
        }
        const float* e = E + (size_t)bidx * DIM;
        float* o = outQ + (size_t)row * DIM;
#pragma unroll
        for (int j = 0; j < 8; j++) {
            float ev = e[lane + 32 * j];
            o[lane + 32 * j] = ev;
            float d = ev - xr[j];
            lossacc += d * d;
        }
        if (lane == 0) out_idx_f[row] = (float)bidx;
    }
#pragma unroll
    for (int o = 16; o > 0; o >>= 1) lossacc += __shfl_xor_sync(0xffffffffu, lossacc, o);
    if (lane == 0) lsum[warp] = lossacc;
    __syncthreads();
    if (threadIdx.x == 0) {
        float t = 0.0f;
#pragma unroll
        for (int i = 0; i < 8; i++) t += lsum[i];
        atomicAdd(&g_loss, t);
    }
}

// ---------------------------------------------------------------------------
// overflow: full exact scan for rows whose candidate list overflowed (rare)
// ---------------------------------------------------------------------------
__global__ void vq_overflow_kernel(const float* __restrict__ X,
                                   const float* __restrict__ E,
                                   float* __restrict__ outQ,
                                   float* __restrict__ out_idx_f) {
    __shared__ float xs[DIM];
    __shared__ float wv[8];
    __shared__ int   wi_[8];
    int cnt = g_ovf_cnt;
    for (int f = blockIdx.x; f < cnt; f += gridDim.x) {
        int row = g_ovf[f];
        __syncthreads();
        if (threadIdx.x < DIM) xs[threadIdx.x] = X[(size_t)row * DIM + threadIdx.x];
        __syncthreads();
        float bv = -3.402823e38f;
        int bi = 0;
        for (int j = threadIdx.x; j < NUM_EMB; j += 256) {
            const float4* e4 = (const float4*)(E + (size_t)j * DIM);
            float dot = 0.0f;
#pragma unroll 8
            for (int k = 0; k < 64; k++) {
                float4 e = e4[k];
                dot += xs[k * 4 + 0] * e.x + xs[k * 4 + 1] * e.y
                     + xs[k * 4 + 2] * e.z + xs[k * 4 + 3] * e.w;
            }
            float sc = dot - g_half_sq[j];
            if (sc > bv) { bv = sc; bi = j; }
        }
#pragma unroll
        for (int o = 16; o > 0; o >>= 1) {
            float ov = __shfl_xor_sync(0xffffffffu, bv, o);
            int   oi = __shfl_xor_sync(0xffffffffu, bi, o);
            if (ov > bv || (ov == bv && oi < bi)) { bv = ov; bi = oi; }
        }
        if ((threadIdx.x & 31) == 0) { wv[threadIdx.x >> 5] = bv; wi_[threadIdx.x >> 5] = bi; }
        __syncthreads();
        if (threadIdx.x == 0) {
            float fbv = wv[0]; int fbi = wi_[0];
#pragma unroll
            for (int t = 1; t < 8; t++)
                if (wv[t] > fbv || (wv[t] == fbv && wi_[t] < fbi)) { fbv = wv[t]; fbi = wi_[t]; }
            wi_[0] = fbi;
        }
        __syncthreads();
        int bidx = wi_[0];
        // gather + loss for this row
        float part = 0.0f;
        if (threadIdx.x < DIM) {
            float ev = E[(size_t)bidx * DIM + threadIdx.x];
            outQ[(size_t)row * DIM + threadIdx.x] = ev;
            float d = ev - xs[threadIdx.x];
            part = d * d;
        }
#pragma unroll
        for (int o = 16; o > 0; o >>= 1) part += __shfl_xor_sync(0xffffffffu, part, o);
        if ((threadIdx.x & 31) == 0) wv[threadIdx.x >> 5] = part;
        __syncthreads();
        if (threadIdx.x == 0) {
            float t = 0.0f;
#pragma unroll
            for (int i = 0; i < 8; i++) t += wv[i];
            atomicAdd(&g_loss, t);
            out_idx_f[row] = (float)bidx;
        }
        __syncthreads();
    }
}

__global__ void vq_finalize_kernel(float* __restrict__ out_loss) {
    *out_loss = g_loss * (1.0f / (float)Q_ELEMS);
}

extern "C" void kernel_launch(void* const* d_in, const int* in_sizes, int n_in,
                              void* d_out, int out_size) {
    const float* X = (const float*)d_in[0];
    const float* E = (const float*)d_in[1];
    float* out     = (float*)d_out;
    float* outQ    = out;
    float* outLoss = out + Q_ELEMS;
    float* outIdxF = out + Q_ELEMS + 1;

    cudaFuncSetAttribute(vq_main_kernel,
                         cudaFuncAttributeMaxDynamicSharedMemorySize, SMEM_TOTAL);

    vq_prep_kernel<<<NUM_EMB / 8, 256>>>(E);
    vq_splitE_kernel<<<NUM_EMB * 64 / 256, 256>>>(E);
    vq_main_kernel<<<NROWS / BM, 256, SMEM_TOTAL>>>(X);
    vq_phase2_kernel<<<NROWS / 8, 256>>>(X, E, outQ, outIdxF);
    vq_overflow_kernel<<<512, 256>>>(X, E, outQ, outIdxF);
    vq_finalize_kernel<<<1, 1>>>(outLoss);
}

// round 6
// speedup vs baseline: 2.8378x; 1.1082x over previous
#include <cuda_runtime.h>
#include <cuda_bf16.h>
#include <cstdint>

#define NUM_EMB 4096
#define DIM     256
#define NROWS   65536
#define Q_ELEMS (NROWS * DIM)
#define DELTA   0.75f
#define CAP     48

#define BM 128
#define BN 128
#define KITERS  8                   // 256 K / 32 per iter
#define CH_PER_CTA 16               // N-split: each CTA scans 2048 embeddings
#define CTA_ITERS (CH_PER_CTA * KITERS)

// ---- device scratch ----
__device__ __nv_bfloat16 g_Ebf[NUM_EMB * DIM];
__device__ float    g_half_sq[NUM_EMB];
__device__ uint32_t g_rowmax_u[NROWS];             // fenc-encoded global row max
__device__ int      g_cnt[NROWS];
__device__ uint2    g_cand[(size_t)NROWS * CAP];   // {score bits, n}
__device__ int      g_ovf[NROWS];
__device__ int      g_ovf_cnt;
__device__ float    g_loss;

// ---- smem layout (dynamic) ----
#define SM_A     0
#define A_BYTES  (128 * 512)
#define SM_B     A_BYTES
#define B_STAGE  8192
#define SM_HS    (SM_B + 3 * B_STAGE)
#define SM_RM    (SM_HS + 16384)
#define SMEM_TOTAL (SM_RM + 512)

__device__ __forceinline__ uint32_t smem_to_u32(const void* p) {
    uint32_t a;
    asm("{ .reg .u64 t; cvta.to.shared.u64 t, %1; cvt.u32.u64 %0, t; }" : "=r"(a) : "l"(p));
    return a;
}

#define LDSM_X4(r0, r1, r2, r3, addr) \
    asm volatile("ldmatrix.sync.aligned.m8n8.x4.shared.b16 {%0,%1,%2,%3}, [%4];" \
        : "=r"(r0), "=r"(r1), "=r"(r2), "=r"(r3) : "r"(addr))

#define MMA_BF16(d, a, b0, b1) \
    asm volatile("mma.sync.aligned.m16n8k16.row.col.f32.bf16.bf16.f32 " \
        "{%0,%1,%2,%3},{%4,%5,%6,%7},{%8,%9},{%0,%1,%2,%3};" \
        : "+f"((d)[0]), "+f"((d)[1]), "+f"((d)[2]), "+f"((d)[3]) \
        : "r"((a)[0]), "r"((a)[1]), "r"((a)[2]), "r"((a)[3]), "r"(b0), "r"(b1))

#define CP_ASYNC16(dst, src) \
    asm volatile("cp.async.cg.shared.global [%0], [%1], 16;" :: "r"(dst), "l"(src) : "memory")
#define CP_ASYNC_COMMIT() asm volatile("cp.async.commit_group;" ::: "memory")
#define CP_ASYNC_WAIT1()  asm volatile("cp.async.wait_group 1;" ::: "memory")

__device__ __forceinline__ uint32_t fenc(float f) {
    uint32_t u = __float_as_uint(f);
    return (u & 0x80000000u) ? ~u : (u | 0x80000000u);
}
__device__ __forceinline__ float fdec(uint32_t k) {
    uint32_t u = (k & 0x80000000u) ? (k & 0x7fffffffu) : ~k;
    return __uint_as_float(u);
}

// ---------------------------------------------------------------------------
// prep: 0.5*|e|^2, zero counters + global rowmax
// ---------------------------------------------------------------------------
__global__ void vq_prep_kernel(const float* __restrict__ E) {
    int gid = blockIdx.x * blockDim.x + threadIdx.x;
    if (gid == 0) { g_loss = 0.0f; g_ovf_cnt = 0; }
    if (gid < NROWS) { g_cnt[gid] = 0; g_rowmax_u[gid] = 0u; }
    int warp = gid >> 5;
    int lane = threadIdx.x & 31;
    if (warp >= NUM_EMB) return;
    const float4* row = (const float4*)(E + (size_t)warp * DIM);
    float s = 0.0f;
#pragma unroll
    for (int i = 0; i < 2; i++) {
        float4 v = row[lane + 32 * i];
        s += v.x * v.x + v.y * v.y + v.z * v.z + v.w * v.w;
    }
#pragma unroll
    for (int o = 16; o > 0; o >>= 1) s += __shfl_xor_sync(0xffffffffu, s, o);
    if (lane == 0) g_half_sq[warp] = 0.5f * s;
}

// ---------------------------------------------------------------------------
// splitE: E fp32 -> bf16
// ---------------------------------------------------------------------------
__global__ void vq_splitE_kernel(const float* __restrict__ E) {
    int i = blockIdx.x * blockDim.x + threadIdx.x;
    if (i >= NUM_EMB * 64) return;
    float4 v = ((const float4*)E)[i];
    __nv_bfloat16 h[4] = {__float2bfloat16(v.x), __float2bfloat16(v.y),
                          __float2bfloat16(v.z), __float2bfloat16(v.w)};
    ((uint2*)g_Ebf)[i] = *(uint2*)h;
}

// ---------------------------------------------------------------------------
// B stage loader
// ---------------------------------------------------------------------------
__device__ __forceinline__ void load_B_stage(uint32_t sb, int stage, int chunk,
                                             int kt, int tid) {
    const __nv_bfloat16* src0 = g_Ebf + (size_t)(chunk * BN) * DIM + kt * 32;
    uint32_t dstb = sb + SM_B + stage * B_STAGE;
#pragma unroll
    for (int j = 0; j < 2; j++) {
        int cid = tid + 256 * j;
        int n = cid >> 2, c = cid & 3;
        const void* src = src0 + (size_t)n * DIM + c * 8;
        uint32_t dst = dstb + (uint32_t)((n >> 1) * 128)
                     + ((uint32_t)(((((n & 1) << 2) | c) ^ ((n >> 1) & 7))) << 4);
        CP_ASYNC16(dst, src);
    }
}

// ---------------------------------------------------------------------------
// main: bf16 screening GEMM + candidate collection
// grid = 1024: bid>>1 = M-tile, bid&1 = N-half (16 chunks)
// ---------------------------------------------------------------------------
__global__ __launch_bounds__(256, 1)
void vq_main_kernel(const float* __restrict__ X) {
    extern __shared__ char smem[];
    uint32_t sb = smem_to_u32(smem);
    const int tid = threadIdx.x;
    const int l = tid & 31, wid = tid >> 5;
    const int wM = wid & 1, wN = wid >> 1;
    const int row0 = (blockIdx.x >> 1) * BM;
    const int chunk0 = (blockIdx.x & 1) * CH_PER_CTA;
    uint32_t* rmax = (uint32_t*)(smem + SM_RM);

    for (int i = tid; i < NUM_EMB / 4; i += 256)
        ((float4*)(smem + SM_HS))[i] = ((const float4*)g_half_sq)[i];
    if (tid < BM) rmax[tid] = 0u;

    // A fill: xh bf16, swizzled, row stride 512B
    for (int i = tid; i < BM * 64; i += 256) {
        int row = i >> 6, q = i & 63;
        float4 v = ((const float4*)(X + (size_t)(row0 + row) * DIM))[q];
        __nv_bfloat16 h[4] = {__float2bfloat16(v.x), __float2bfloat16(v.y),
                              __float2bfloat16(v.z), __float2bfloat16(v.w)};
        int c = q >> 1;
        uint32_t off = (uint32_t)row * 512 + ((uint32_t)(c >> 3) << 7)
                     + ((uint32_t)((c & 7) ^ (row & 7)) << 4) + ((uint32_t)(q & 1) << 3);
        *(uint2*)(smem + SM_A + off) = *(uint2*)h;
    }

    load_B_stage(sb, 0, chunk0, 0, tid); CP_ASYNC_COMMIT();
    load_B_stage(sb, 1, chunk0, 1, tid); CP_ASYNC_COMMIT();

    const int clA = l >> 4;
    const int lsw = l & 7;
    uint32_t abase[4];
#pragma unroll
    for (int mt = 0; mt < 4; mt++) {
        int rowA = wM * 64 + mt * 16 + (l & 15);
        abase[mt] = sb + SM_A + (uint32_t)rowA * 512;
    }
    uint32_t bblk[2], bswz[2], bc4[2];
#pragma unroll
    for (int ntp = 0; ntp < 2; ntp++) {
        int nloc = wN * 32 + ntp * 16 + (l & 15);
        bblk[ntp] = (uint32_t)(nloc >> 1) * 128;
        bswz[ntp] = (uint32_t)((nloc >> 1) & 7);
        bc4[ntp]  = (uint32_t)((nloc & 1) << 2);
    }

    float acc[4][4][4];
#pragma unroll
    for (int a = 0; a < 4; a++)
#pragma unroll
        for (int b = 0; b < 4; b++)
#pragma unroll
            for (int c = 0; c < 4; c++) acc[a][b][c] = 0.0f;

    int buf = 0, pbuf = 2;
    const float* hsp = (const float*)(smem + SM_HS);

    for (int c = 0; c < CH_PER_CTA; c++) {
        const int chunk = chunk0 + c;
#pragma unroll
        for (int kt = 0; kt < KITERS; kt++) {
            CP_ASYNC_WAIT1();
            __syncthreads();

            uint32_t bbuf = sb + SM_B + buf * B_STAGE;
            int cA0 = kt * 4;
#pragma unroll
            for (int s = 0; s < 2; s++) {
                int cA = cA0 + s * 2 + clA;
                uint32_t offA = ((uint32_t)(cA >> 3) << 7) | ((uint32_t)((cA & 7) ^ lsw) << 4);
                uint32_t a_[4][4];
#pragma unroll
                for (int mt = 0; mt < 4; mt++)
                    LDSM_X4(a_[mt][0], a_[mt][1], a_[mt][2], a_[mt][3], abase[mt] + offA);
                uint32_t cB = (uint32_t)(s * 2 + clA);
                uint32_t bfr[4][2];
#pragma unroll
                for (int ntp = 0; ntp < 2; ntp++) {
                    uint32_t addr = bbuf + bblk[ntp] + (((bc4[ntp] | cB) ^ bswz[ntp]) << 4);
                    uint32_t r0, r1, r2, r3;
                    LDSM_X4(r0, r1, r2, r3, addr);
                    bfr[2 * ntp][0] = r0; bfr[2 * ntp][1] = r2;
                    bfr[2 * ntp + 1][0] = r1; bfr[2 * ntp + 1][1] = r3;
                }
#pragma unroll
                for (int mt = 0; mt < 4; mt++)
#pragma unroll
                    for (int nt = 0; nt < 4; nt++)
                        MMA_BF16(acc[mt][nt], a_[mt], bfr[nt][0], bfr[nt][1]);
            }

            int it = c * KITERS + kt;
            if (it + 2 < CTA_ITERS) {
                int pit = it + 2;
                load_B_stage(sb, pbuf, chunk0 + (pit >> 3), pit & 7, tid);
            }
            CP_ASYNC_COMMIT();
            pbuf = (pbuf == 2) ? 0 : pbuf + 1;
            buf  = (buf == 2) ? 0 : buf + 1;
        }

        // ---- epilogue for this chunk ----
        const int nbase = chunk * BN + wN * 32 + (l & 3) * 2;
        float hs8[8];
#pragma unroll
        for (int nt = 0; nt < 4; nt++) {
            hs8[nt * 2]     = hsp[nbase + nt * 8];
            hs8[nt * 2 + 1] = hsp[nbase + nt * 8 + 1];
        }
        // pass A: scores into acc, per-slot max -> smem atomicMax
#pragma unroll
        for (int mt = 0; mt < 4; mt++)
#pragma unroll
            for (int rh = 0; rh < 2; rh++) {
                int r_loc = wM * 64 + mt * 16 + (l >> 2) + rh * 8;
                float smax = -3.402823e38f;
#pragma unroll
                for (int nt = 0; nt < 4; nt++)
#pragma unroll
                    for (int cj = 0; cj < 2; cj++) {
                        float sc = acc[mt][nt][rh * 2 + cj] - hs8[nt * 2 + cj];
                        acc[mt][nt][rh * 2 + cj] = sc;
                        smax = fmaxf(smax, sc);
                    }
                atomicMax(&rmax[r_loc], fenc(smax));
            }
        __syncthreads();
        // pass B: append candidates within DELTA of (local) row max
#pragma unroll
        for (int mt = 0; mt < 4; mt++)
#pragma unroll
            for (int rh = 0; rh < 2; rh++) {
                int r_loc = wM * 64 + mt * 16 + (l >> 2) + rh * 8;
                float window = fdec(rmax[r_loc]) - DELTA;
                int grow = row0 + r_loc;
#pragma unroll
                for (int nt = 0; nt < 4; nt++)
#pragma unroll
                    for (int cj = 0; cj < 2; cj++) {
                        float sc = acc[mt][nt][rh * 2 + cj];
                        if (sc > window) {
                            int pos = atomicAdd(&g_cnt[grow], 1);
                            if (pos < CAP) {
                                g_cand[(size_t)grow * CAP + pos] =
                                    make_uint2(__float_as_uint(sc),
                                               (uint32_t)(nbase + nt * 8 + cj));
                            }
                        }
                        acc[mt][nt][rh * 2 + cj] = 0.0f;
                    }
            }
    }

    __syncthreads();
    if (tid < BM) atomicMax(&g_rowmax_u[row0 + tid], rmax[tid]);
}

// ---------------------------------------------------------------------------
// phase 2: exact fp32 on candidates + gather + loss (1 warp per row)
// ---------------------------------------------------------------------------
__global__ __launch_bounds__(256)
void vq_phase2_kernel(const float* __restrict__ X, const float* __restrict__ E,
                      float* __restrict__ outQ, float* __restrict__ out_idx_f) {
    __shared__ float lsum[8];
    int warp = threadIdx.x >> 5, lane = threadIdx.x & 31;
    int row = blockIdx.x * 8 + warp;
    float lossacc = 0.0f;
    int cnt = g_cnt[row];
    float xr[8];
    const float* xrow = X + (size_t)row * DIM;
#pragma unroll
    for (int j = 0; j < 8; j++) xr[j] = xrow[lane + 32 * j];

    if (cnt > CAP) {
        if (lane == 0) { int p = atomicAdd(&g_ovf_cnt, 1); g_ovf[p] = row; }
    } else {
        float window = fdec(g_rowmax_u[row]) - DELTA;
        float best = -3.402823e38f;
        int bidx = NUM_EMB;
        for (int c = 0; c < cnt; c++) {
            uint2 cd = g_cand[(size_t)row * CAP + c];
            float apx = __uint_as_float(cd.x);
            if (apx < window) continue;
            int n = (int)cd.y;
            const float* e = E + (size_t)n * DIM;
            float dot = 0.0f;
#pragma unroll
            for (int j = 0; j < 8; j++) dot = fmaf(xr[j], e[lane + 32 * j], dot);
#pragma unroll
            for (int o = 16; o > 0; o >>= 1) dot += __shfl_xor_sync(0xffffffffu, dot, o);
            float sc = dot - g_half_sq[n];
            if (sc > best || (sc == best && n < bidx)) { best = sc; bidx = n; }
        }
        const float* e = E + (size_t)bidx * DIM;
        float* o = outQ + (size_t)row * DIM;
#pragma unroll
        for (int j = 0; j < 8; j++) {
            float ev = e[lane + 32 * j];
            o[lane + 32 * j] = ev;
            float d = ev - xr[j];
            lossacc += d * d;
        }
        if (lane == 0) out_idx_f[row] = (float)bidx;
    }
#pragma unroll
    for (int o = 16; o > 0; o >>= 1) lossacc += __shfl_xor_sync(0xffffffffu, lossacc, o);
    if (lane == 0) lsum[warp] = lossacc;
    __syncthreads();
    if (threadIdx.x == 0) {
        float t = 0.0f;
#pragma unroll
        for (int i = 0; i < 8; i++) t += lsum[i];
        atomicAdd(&g_loss, t);
    }
}

// ---------------------------------------------------------------------------
// overflow: full exact scan (rare)
// ---------------------------------------------------------------------------
__global__ void vq_overflow_kernel(const float* __restrict__ X,
                                   const float* __restrict__ E,
                                   float* __restrict__ outQ,
                                   float* __restrict__ out_idx_f) {
    __shared__ float xs[DIM];
    __shared__ float wv[8];
    __shared__ int   wi_[8];
    int cnt = g_ovf_cnt;
    for (int f = blockIdx.x; f < cnt; f += gridDim.x) {
        int row = g_ovf[f];
        __syncthreads();
        if (threadIdx.x < DIM) xs[threadIdx.x] = X[(size_t)row * DIM + threadIdx.x];
        __syncthreads();
        float bv = -3.402823e38f;
        int bi = 0;
        for (int j = threadIdx.x; j < NUM_EMB; j += 256) {
            const float4* e4 = (const float4*)(E + (size_t)j * DIM);
            float dot = 0.0f;
#pragma unroll 8
            for (int k = 0; k < 64; k++) {
                float4 e = e4[k];
                dot += xs[k * 4 + 0] * e.x + xs[k * 4 + 1] * e.y
                     + xs[k * 4 + 2] * e.z + xs[k * 4 + 3] * e.w;
            }
            float sc = dot - g_half_sq[j];
            if (sc > bv) { bv = sc; bi = j; }
        }
#pragma unroll
        for (int o = 16; o > 0; o >>= 1) {
            float ov = __shfl_xor_sync(0xffffffffu, bv, o);
            int   oi = __shfl_xor_sync(0xffffffffu, bi, o);
            if (ov > bv || (ov == bv && oi < bi)) { bv = ov; bi = oi; }
        }
        if ((threadIdx.x & 31) == 0) { wv[threadIdx.x >> 5] = bv; wi_[threadIdx.x >> 5] = bi; }
        __syncthreads();
        if (threadIdx.x == 0) {
            float fbv = wv[0]; int fbi = wi_[0];
#pragma unroll
            for (int t = 1; t < 8; t++)
                if (wv[t] > fbv || (wv[t] == fbv && wi_[t] < fbi)) { fbv = wv[t]; fbi = wi_[t]; }
            wi_[0] = fbi;
        }
        __syncthreads();
        int bidx = wi_[0];
        float part = 0.0f;
        if (threadIdx.x < DIM) {
            float ev = E[(size_t)bidx * DIM + threadIdx.x];
            outQ[(size_t)row * DIM + threadIdx.x] = ev;
            float d = ev - xs[threadIdx.x];
            part = d * d;
        }
#pragma unroll
        for (int o = 16; o > 0; o >>= 1) part += __shfl_xor_sync(0xffffffffu, part, o);
        if ((threadIdx.x & 31) == 0) wv[threadIdx.x >> 5] = part;
        __syncthreads();
        if (threadIdx.x == 0) {
            float t = 0.0f;
#pragma unroll
            for (int i = 0; i < 8; i++) t += wv[i];
            atomicAdd(&g_loss, t);
            out_idx_f[row] = (float)bidx;
        }
        __syncthreads();
    }
}

__global__ void vq_finalize_kernel(float* __restrict__ out_loss) {
    *out_loss = g_loss * (1.0f / (float)Q_ELEMS);
}

extern "C" void kernel_launch(void* const* d_in, const int* in_sizes, int n_in,
                              void* d_out, int out_size) {
    const float* X = (const float*)d_in[0];
    const float* E = (const float*)d_in[1];
    float* out     = (float*)d_out;
    float* outQ    = out;
    float* outLoss = out + Q_ELEMS;
    float* outIdxF = out + Q_ELEMS + 1;

    cudaFuncSetAttribute(vq_main_kernel,
                         cudaFuncAttributeMaxDynamicSharedMemorySize, SMEM_TOTAL);

    vq_prep_kernel<<<NUM_EMB / 8, 256>>>(E);
    vq_splitE_kernel<<<NUM_EMB * 64 / 256, 256>>>(E);
    vq_main_kernel<<<1024, 256, SMEM_TOTAL>>>(X);
    vq_phase2_kernel<<<NROWS / 8, 256>>>(X, E, outQ, outIdxF);
    vq_overflow_kernel<<<128, 256>>>(X, E, outQ, outIdxF);
    vq_finalize_kernel<<<1, 1>>>(outLoss);
}